// round 6
// baseline (speedup 1.0000x reference)
#include <cuda_runtime.h>
#include <cuda_bf16.h>
#include <math.h>
#include <stdint.h>

// ---------------- problem constants ----------------
#define NTOK  49152
#define NSEQ  2048
#define Bdim  16
#define Tdim  128
#define Jm    24
#define Hdim  256
#define H3    768
#define H4    1024
#define Lnum  4
#define Mnum  12
#define RANKv 8
#define HEADS 8
#define DH    32
#define TOKPB 3072

__constant__ int c_nj[Mnum] = {8,10,12,14,16,18,20,22,24,9,13,17};

// ---------------- scratch ----------------
__device__ float         g_x   [(size_t)NTOK * Hdim];
__device__ __nv_bfloat16 g_h   [(size_t)NTOK * Hdim];
__device__ __nv_bfloat16 g_qkv [(size_t)NTOK * H3 ];
__device__ __nv_bfloat16 g_o   [(size_t)NTOK * Hdim];
__device__ __nv_bfloat16 g_midb[(size_t)NTOK * H4 ];
__device__ float         g_tmp [(size_t)NTOK * RANKv];
__device__ __nv_bfloat16 g_wt  [(size_t)Lnum * 786432];
__device__ int           g_cat [Bdim * Jm];

// ---------------- helpers ----------------
__device__ __forceinline__ uint32_t smem_u32(const void* p) {
    uint32_t a;
    asm("{ .reg .u64 t; cvta.to.shared.u64 t, %1; cvt.u32.u64 %0, t; }" : "=r"(a) : "l"(p));
    return a;
}
__device__ __forceinline__ void cp16(uint32_t dst, const void* src) {
    asm volatile("cp.async.cg.shared.global [%0], [%1], 16;" :: "r"(dst), "l"(src));
}
__device__ __forceinline__ void cp_commit() { asm volatile("cp.async.commit_group;"); }
__device__ __forceinline__ void ldm_x4(uint32_t& r0, uint32_t& r1, uint32_t& r2, uint32_t& r3, uint32_t a) {
    asm volatile("ldmatrix.sync.aligned.m8n8.x4.shared.b16 {%0,%1,%2,%3}, [%4];"
                 : "=r"(r0), "=r"(r1), "=r"(r2), "=r"(r3) : "r"(a));
}
__device__ __forceinline__ void mma16816(float* c, const uint32_t* a, const uint32_t* b) {
    asm volatile("mma.sync.aligned.m16n8k16.row.col.f32.bf16.bf16.f32 "
                 "{%0,%1,%2,%3},{%4,%5,%6,%7},{%8,%9},{%0,%1,%2,%3};"
                 : "+f"(c[0]), "+f"(c[1]), "+f"(c[2]), "+f"(c[3])
                 : "r"(a[0]), "r"(a[1]), "r"(a[2]), "r"(a[3]), "r"(b[0]), "r"(b[1]));
}
__device__ __forceinline__ uint32_t pack2bf(float x, float y) {
    __nv_bfloat162 h = __floats2bfloat162_rn(x, y);
    return *reinterpret_cast<uint32_t*>(&h);
}
__device__ __forceinline__ float gelu_tanh(float x) {
    float x3 = x * x * x;
    return 0.5f * x * (1.f + tanhf(0.7978845608028654f * (x + 0.044715f * x3)));
}

// ---------------- unified HMMA GEMM: 128x256 CTA tile, 512 threads ----------------
// warp grid 4(wm) x 4(wn); warp tile 32 rows x 64 cols; K-chunk 64; 3-stage cp.async.
// EPI 1: Cb = bf16(gelu(acc+bias))
// EPI 3: Cb = bf16(acc+bias+lora)
// EPI 4: x += gsc*(acc+bias), then fused LayerNorm over full 256-col rows -> Hout (TO)
#define TILEA  16384                 // 128 x 128B
#define TILEB2 32768                 // 256 x 128B
#define STAGEB (TILEA + TILEB2)      // 49152
#define NSTG   3
#define GSMEM  (NSTG * STAGEB)       // 147456

template<int EPI, typename TO>
__global__ void __launch_bounds__(512)
hmma256_kernel(const __nv_bfloat16* __restrict__ A, const __nv_bfloat16* __restrict__ Bt,
               float* __restrict__ C, __nv_bfloat16* __restrict__ Cb,
               const float* __restrict__ bias, const float* __restrict__ gsc,
               const float* __restrict__ ltmp, const float* __restrict__ lB,
               const int* __restrict__ midx,
               const float* __restrict__ lnS, const float* __restrict__ lnB,
               TO* __restrict__ Hout,
               int K, int N)
{
    extern __shared__ char dynsm[];

    int tid = threadIdx.x, lane = tid & 31, wid = tid >> 5;
    int wm = wid & 3, wn = wid >> 2;
    int brow = blockIdx.y * 128, bcol = blockIdx.x * 256;

    float acc[2][8][4];
    #pragma unroll
    for (int i = 0; i < 2; i++)
        #pragma unroll
        for (int j = 0; j < 8; j++)
            #pragma unroll
            for (int q = 0; q < 4; q++) acc[i][j][q] = 0.f;

    int nch = K >> 6;

    // A: 128x64 bf16 (1024 16B chunks), B: 256x64 (2048 chunks); swizzle slot = cc^(row&7)
    auto load_tiles = [&](int ch, int stage) {
        const __nv_bfloat16* As = A + (size_t)brow * K + ch * 64;
        const __nv_bfloat16* Bs = Bt + (size_t)bcol * K + ch * 64;
        uint32_t da = smem_u32(dynsm + stage * STAGEB);
        uint32_t db = da + TILEA;
        #pragma unroll
        for (int hh = 0; hh < 2; hh++) {
            int cid = tid + hh * 512;
            int row = cid >> 3, cc = cid & 7;
            cp16(da + (uint32_t)(row * 128 + ((cc ^ (row & 7)) * 16)),
                 As + (size_t)row * K + cc * 8);
        }
        #pragma unroll
        for (int hh = 0; hh < 4; hh++) {
            int cid = tid + hh * 512;
            int row = cid >> 3, cc = cid & 7;
            cp16(db + (uint32_t)(row * 128 + ((cc ^ (row & 7)) * 16)),
                 Bs + (size_t)row * K + cc * 8);
        }
        cp_commit();
    };

    load_tiles(0, 0);
    load_tiles(1, 1);

    for (int ch = 0; ch < nch; ch++) {
        asm volatile("cp.async.wait_group 1;");
        __syncthreads();

        int st = ch % NSTG;
        uint32_t sa = smem_u32(dynsm + st * STAGEB);
        uint32_t sb = sa + TILEA;
        int rsel = lane & 15, ksel = lane >> 4;

        #pragma unroll
        for (int ks = 0; ks < 4; ks++) {
            int chunk = ks * 2 + ksel;
            uint32_t a[2][4];
            #pragma unroll
            for (int mf = 0; mf < 2; mf++) {
                int ar = wm * 32 + mf * 16 + rsel;
                ldm_x4(a[mf][0], a[mf][1], a[mf][2], a[mf][3],
                       sa + (uint32_t)(ar * 128 + ((chunk ^ (ar & 7)) * 16)));
            }
            uint32_t b[8][2];
            #pragma unroll
            for (int nf2 = 0; nf2 < 4; nf2++) {
                uint32_t r0, r1, r2, r3;
                int br = wn * 64 + nf2 * 16 + rsel;
                ldm_x4(r0, r1, r2, r3,
                       sb + (uint32_t)(br * 128 + ((chunk ^ (br & 7)) * 16)));
                b[nf2 * 2 + 0][0] = r0; b[nf2 * 2 + 0][1] = r2;
                b[nf2 * 2 + 1][0] = r1; b[nf2 * 2 + 1][1] = r3;
            }
            #pragma unroll
            for (int mf = 0; mf < 2; mf++)
                #pragma unroll
                for (int nf = 0; nf < 8; nf++)
                    mma16816(acc[mf][nf], a[mf], b[nf]);
        }

        if (ch + 2 < nch) load_tiles(ch + 2, (ch + 2) % NSTG);
        else              cp_commit();
    }

    int g = lane >> 2, tg = lane & 3;

    // ---- EPI 3: LoRA staging (m constant per 128-row tile) ----
    float* lb_s  = (float*)dynsm;             // [8][256]
    float* tmp_s = (float*)(dynsm + 8192);    // [128][9]
    if (EPI == 3) {
        __syncthreads();
        int m = midx[brow / TOKPB];
        #pragma unroll
        for (int hh = 0; hh < 4; hh++) {
            int i = tid + hh * 512;           // 2048
            int q = i >> 8, c = i & 255;
            lb_s[q * 256 + c] = lB[((size_t)m * RANKv + q) * N + bcol + c];
        }
        #pragma unroll
        for (int hh = 0; hh < 3; hh++) {
            int i = tid + hh * 512;
            if (i < 1152) {
                int r = i / 9, q2 = i % 9;
                if (q2 < 8) tmp_s[i] = ltmp[(size_t)(brow + r) * RANKv + q2];
            }
        }
        __syncthreads();
    }

    // ---- main epilogue pass: bias (+lora) (+rmw) ----
    #pragma unroll
    for (int mf = 0; mf < 2; mf++) {
        int rl = wm * 32 + mf * 16 + g;
        int r0 = brow + rl;
        float t0[8], t1[8];
        if (EPI == 3) {
            #pragma unroll
            for (int q = 0; q < 8; q++) { t0[q] = tmp_s[rl * 9 + q]; t1[q] = tmp_s[(rl + 8) * 9 + q]; }
        }
        #pragma unroll
        for (int nf = 0; nf < 8; nf++) {
            int cl  = wn * 64 + nf * 8 + tg * 2;
            int col = bcol + cl;
            float b0 = bias[col], b1 = bias[col + 1];
            float v0 = acc[mf][nf][0] + b0, v1 = acc[mf][nf][1] + b1;
            float v2 = acc[mf][nf][2] + b0, v3 = acc[mf][nf][3] + b1;
            if (EPI == 1) {
                *(uint32_t*)(Cb + (size_t)r0 * N + col)       = pack2bf(gelu_tanh(v0), gelu_tanh(v1));
                *(uint32_t*)(Cb + (size_t)(r0 + 8) * N + col) = pack2bf(gelu_tanh(v2), gelu_tanh(v3));
            } else if (EPI == 3) {
                float a00 = 0.f, a01 = 0.f, a10 = 0.f, a11 = 0.f;
                #pragma unroll
                for (int q = 0; q < 8; q++) {
                    float w0 = lb_s[q * 256 + cl], w1 = lb_s[q * 256 + cl + 1];
                    a00 += t0[q] * w0; a01 += t0[q] * w1;
                    a10 += t1[q] * w0; a11 += t1[q] * w1;
                }
                *(uint32_t*)(Cb + (size_t)r0 * N + col)       = pack2bf(v0 + a00, v1 + a01);
                *(uint32_t*)(Cb + (size_t)(r0 + 8) * N + col) = pack2bf(v2 + a10, v3 + a11);
            } else {  // EPI 4: residual rmw, keep updated x in acc
                float s0 = gsc[col], s1 = gsc[col + 1];
                float2 o0 = *(float2*)(C + (size_t)r0 * N + col);
                float2 o1 = *(float2*)(C + (size_t)(r0 + 8) * N + col);
                o0.x += s0 * v0; o0.y += s1 * v1;
                o1.x += s0 * v2; o1.y += s1 * v3;
                *(float2*)(C + (size_t)r0 * N + col)       = o0;
                *(float2*)(C + (size_t)(r0 + 8) * N + col) = o1;
                acc[mf][nf][0] = o0.x; acc[mf][nf][1] = o0.y;
                acc[mf][nf][2] = o1.x; acc[mf][nf][3] = o1.y;
            }
        }
    }

    // ---- EPI 4: fused LayerNorm over the CTA's full 256-col rows ----
    if (EPI == 4) {
        float* ssum = (float*)dynsm;             // [128][4]
        float* ssq  = ssum + 512;                // [128][4]
        float* smu  = ssq + 512;                 // [128]
        float* srs  = smu + 128;                 // [128]
        __syncthreads();   // smem reuse

        #pragma unroll
        for (int mf = 0; mf < 2; mf++) {
            #pragma unroll
            for (int half = 0; half < 2; half++) {
                float ps = 0.f, pq = 0.f;
                #pragma unroll
                for (int nf = 0; nf < 8; nf++) {
                    float v0 = acc[mf][nf][half * 2 + 0];
                    float v1 = acc[mf][nf][half * 2 + 1];
                    ps += v0 + v1;
                    pq += v0 * v0 + v1 * v1;
                }
                ps += __shfl_xor_sync(0xffffffffu, ps, 1);
                pq += __shfl_xor_sync(0xffffffffu, pq, 1);
                ps += __shfl_xor_sync(0xffffffffu, ps, 2);
                pq += __shfl_xor_sync(0xffffffffu, pq, 2);
                if (tg == 0) {
                    int rl = wm * 32 + mf * 16 + half * 8 + g;
                    ssum[rl * 4 + wn] = ps;
                    ssq [rl * 4 + wn] = pq;
                }
            }
        }
        __syncthreads();
        if (tid < 128) {
            float s = ssum[tid * 4] + ssum[tid * 4 + 1] + ssum[tid * 4 + 2] + ssum[tid * 4 + 3];
            float q = ssq [tid * 4] + ssq [tid * 4 + 1] + ssq [tid * 4 + 2] + ssq [tid * 4 + 3];
            float mu = s * (1.f / 256.f);
            float var = fmaxf(q * (1.f / 256.f) - mu * mu, 0.f);
            smu[tid] = mu;
            srs[tid] = rsqrtf(var + 1e-5f);
        }
        __syncthreads();

        #pragma unroll
        for (int mf = 0; mf < 2; mf++) {
            int rl = wm * 32 + mf * 16 + g;
            float mu0 = smu[rl],     rs0 = srs[rl];
            float mu1 = smu[rl + 8], rs1 = srs[rl + 8];
            int r0 = brow + rl;
            #pragma unroll
            for (int nf = 0; nf < 8; nf++) {
                int col = bcol + wn * 64 + nf * 8 + tg * 2;
                float sc0 = lnS[col], sc1 = lnS[col + 1];
                float bi0 = lnB[col], bi1 = lnB[col + 1];
                float h0 = (acc[mf][nf][0] - mu0) * rs0 * sc0 + bi0;
                float h1 = (acc[mf][nf][1] - mu0) * rs0 * sc1 + bi1;
                float h2 = (acc[mf][nf][2] - mu1) * rs1 * sc0 + bi0;
                float h3 = (acc[mf][nf][3] - mu1) * rs1 * sc1 + bi1;
                if constexpr (sizeof(TO) == 2) {
                    *(uint32_t*)((__nv_bfloat16*)Hout + (size_t)r0 * 256 + col)       = pack2bf(h0, h1);
                    *(uint32_t*)((__nv_bfloat16*)Hout + (size_t)(r0 + 8) * 256 + col) = pack2bf(h2, h3);
                } else {
                    *(float2*)((float*)Hout + (size_t)r0 * 256 + col)       = make_float2(h0, h1);
                    *(float2*)((float*)Hout + (size_t)(r0 + 8) * 256 + col) = make_float2(h2, h3);
                }
            }
        }
    }
}

// ---------------- weight transpose-convert ----------------
__global__ void transpose_bf16_kernel(const float* __restrict__ src,
                                      __nv_bfloat16* __restrict__ dst, int K, int N,
                                      size_t sstride, size_t dstride)
{
    src += blockIdx.z * sstride;
    dst += blockIdx.z * dstride;
    __shared__ float t[32][33];
    int kb = blockIdx.y * 32, nb = blockIdx.x * 32;
    int x = threadIdx.x, y = threadIdx.y;
    #pragma unroll
    for (int i = 0; i < 32; i += 8)
        t[y + i][x] = src[(size_t)(kb + y + i) * N + nb + x];
    __syncthreads();
    #pragma unroll
    for (int i = 0; i < 32; i += 8)
        dst[(size_t)(nb + y + i) * K + kb + x] = __float2bfloat16(t[x][y + i]);
}

// ---------------- mask-format detection + category ----------------
__global__ void detect_cat_kernel(const unsigned char* __restrict__ sm,
                                  const unsigned char* __restrict__ hm,
                                  const unsigned char* __restrict__ gm,
                                  int* __restrict__ cat)
{
    __shared__ int offbyte, i32bad, f32bad, f32one;
    __shared__ int fmt_s;
    if (threadIdx.x == 0) { offbyte = 0; i32bad = 0; f32bad = 0; f32one = 0; }
    __syncthreads();
    const unsigned char* bufs[3] = {sm, hm, gm};
    for (int bi = 0; bi < 3; bi++) {
        const unsigned char* p = bufs[bi];
        for (int i = threadIdx.x; i < NTOK; i += blockDim.x)
            if ((i & 3) != 0 && p[i] != 0) atomicOr(&offbyte, 1);
        const int*   pi = (const int*)p;
        const float* pf = (const float*)p;
        for (int i = threadIdx.x; i < NTOK / 4; i += blockDim.x) {
            int iv = pi[i]; float fv = pf[i];
            if (iv != 0 && iv != 1)     atomicOr(&i32bad, 1);
            if (fv != 0.f && fv != 1.f) atomicOr(&f32bad, 1);
            if (fv == 1.f)              atomicOr(&f32one, 1);
        }
    }
    __syncthreads();
    if (threadIdx.x == 0) {
        int fmt;
        if (!offbyte && !i32bad)    fmt = 1;
        else if (!f32bad && f32one) fmt = 2;
        else                        fmt = 0;
        fmt_s = fmt;
    }
    __syncthreads();
    int fmt = fmt_s;
    for (int idx = threadIdx.x; idx < Bdim * Jm; idx += blockDim.x) {
        int b = idx / Jm, j = idx % Jm;
        int e = b * (Tdim * Jm) + j;
        bool sv, hv, gv;
        if (fmt == 0)      { sv = sm[e] != 0; hv = hm[e] != 0; gv = gm[e] != 0; }
        else if (fmt == 1) { sv = ((const int*)sm)[e] != 0; hv = ((const int*)hm)[e] != 0; gv = ((const int*)gm)[e] != 0; }
        else               { sv = ((const float*)sm)[e] != 0.f; hv = ((const float*)hm)[e] != 0.f; gv = ((const float*)gm)[e] != 0.f; }
        cat[idx] = sv ? 0 : (hv ? 1 : (gv ? 2 : 3));
    }
}

// ---------------- embedding ----------------
__global__ void embed_kernel(const float* __restrict__ act,
                             const int* __restrict__ m_idx, const int* __restrict__ cat,
                             const float* __restrict__ Ws, const float* __restrict__ bs,
                             const float* __restrict__ Wh, const float* __restrict__ bh,
                             const float* __restrict__ Wg, const float* __restrict__ Wact,
                             const float* __restrict__ pos, float* __restrict__ x)
{
    int token = blockIdx.x;
    int c = threadIdx.x;
    int j = token % Jm;
    int b = token / TOKPB;
    int m = m_idx[b];
    int ct = cat[b * Jm + j];
    float a = act[token];
    float e;
    if      (ct == 0) e = a * Ws[c] + bs[c];
    else if (ct == 1) e = a * Wh[c] + bh[c];
    else if (ct == 2) e = a * Wg[m * Hdim + c];
    else              e = 0.f;
    if (ct != 3) e += Wact[c];
    e += pos[((size_t)m * Jm + j) * Hdim + c];
    x[(size_t)token * Hdim + c] = e;
}

// ---------------- standalone layernorm (layer-0 entry only) ----------------
template<typename TO>
__global__ void ln_warp_kernel(const float* __restrict__ in, TO* __restrict__ out,
                               const float* __restrict__ sc, const float* __restrict__ bi)
{
    int token = blockIdx.x * 8 + (threadIdx.x >> 5);
    int lane = threadIdx.x & 31;
    const float4* p = (const float4*)(in + (size_t)token * Hdim);
    float4 a = p[lane], b = p[lane + 32];
    float s = a.x + a.y + a.z + a.w + b.x + b.y + b.z + b.w;
    #pragma unroll
    for (int o = 16; o > 0; o >>= 1) s += __shfl_xor_sync(0xffffffffu, s, o);
    float mu = s * (1.f / Hdim);
    a.x -= mu; a.y -= mu; a.z -= mu; a.w -= mu;
    b.x -= mu; b.y -= mu; b.z -= mu; b.w -= mu;
    float v = a.x*a.x + a.y*a.y + a.z*a.z + a.w*a.w + b.x*b.x + b.y*b.y + b.z*b.z + b.w*b.w;
    #pragma unroll
    for (int o = 16; o > 0; o >>= 1) v += __shfl_xor_sync(0xffffffffu, v, o);
    float r = rsqrtf(v * (1.f / Hdim) + 1e-5f);
    const float4* s4 = (const float4*)sc;
    const float4* b4 = (const float4*)bi;
    float4 sa = s4[lane], sb = s4[lane + 32], ba = b4[lane], bb = b4[lane + 32];
    float o0 = a.x * r * sa.x + ba.x, o1 = a.y * r * sa.y + ba.y;
    float o2 = a.z * r * sa.z + ba.z, o3 = a.w * r * sa.w + ba.w;
    float o4 = b.x * r * sb.x + bb.x, o5 = b.y * r * sb.y + bb.y;
    float o6 = b.z * r * sb.z + bb.z, o7 = b.w * r * sb.w + bb.w;
    if constexpr (sizeof(TO) == 4) {
        float4* q = (float4*)((float*)out + (size_t)token * Hdim);
        q[lane]      = make_float4(o0, o1, o2, o3);
        q[lane + 32] = make_float4(o4, o5, o6, o7);
    } else {
        uint2* q = (uint2*)((__nv_bfloat16*)out + (size_t)token * Hdim);
        q[lane]      = make_uint2(pack2bf(o0, o1), pack2bf(o2, o3));
        q[lane + 32] = make_uint2(pack2bf(o4, o5), pack2bf(o6, o7));
    }
}

// ---------------- LoRA stage 1 ----------------
__global__ void lora_tmp_kernel(const __nv_bfloat16* __restrict__ h,
                                const float* __restrict__ lA,
                                const int* __restrict__ m_idx,
                                float* __restrict__ tmp)
{
    int token = blockIdx.x * 8 + (threadIdx.x >> 5);
    int lane = threadIdx.x & 31;
    int m = m_idx[token / TOKPB];
    const float* A = lA + (size_t)m * Hdim * RANKv;
    float s[8] = {0.f, 0.f, 0.f, 0.f, 0.f, 0.f, 0.f, 0.f};
    #pragma unroll
    for (int d0 = 0; d0 < Hdim; d0 += 32) {
        int d = d0 + lane;
        float hv = __bfloat162float(h[(size_t)token * Hdim + d]);
        const float4* ap = (const float4*)(A + (size_t)d * RANKv);
        float4 a0 = ap[0], a1 = ap[1];
        s[0] += hv * a0.x; s[1] += hv * a0.y; s[2] += hv * a0.z; s[3] += hv * a0.w;
        s[4] += hv * a1.x; s[5] += hv * a1.y; s[6] += hv * a1.z; s[7] += hv * a1.w;
    }
    #pragma unroll
    for (int r = 0; r < 8; r++)
        #pragma unroll
        for (int o = 16; o > 0; o >>= 1) s[r] += __shfl_xor_sync(0xffffffffu, s[r], o);
    if (lane < 8) tmp[(size_t)token * RANKv + lane] = s[lane];
}

// ---------------- attention ----------------
__global__ void attn_kernel(const __nv_bfloat16* __restrict__ qkv, __nv_bfloat16* __restrict__ o,
                            const int* __restrict__ m_idx)
{
    __shared__ float qs[Jm][DH + 1];
    __shared__ float ks[Jm][DH + 1];
    __shared__ float vs[Jm][DH + 1];
    __shared__ float sc[Jm][Jm + 1];
    int n = blockIdx.x, head = blockIdx.y;
    int b = n >> 7;
    int nj = c_nj[m_idx[b]];
    const float scale = 0.17677669529663687f;
    for (int idx = threadIdx.x; idx < Jm * DH; idx += blockDim.x) {
        int j = idx >> 5, d = idx & 31;
        size_t base = ((size_t)(n * Jm + j)) * H3 + head * DH + d;
        qs[j][d] = __bfloat162float(qkv[base]) * scale;
        ks[j][d] = __bfloat162float(qkv[base + Hdim]);
        vs[j][d] = __bfloat162float(qkv[base + 2 * Hdim]);
    }
    __syncthreads();
    for (int idx = threadIdx.x; idx < Jm * Jm; idx += blockDim.x) {
        int i = idx / Jm, j = idx % Jm;
        bool ok = (i < nj && j < nj) || (i == j);
        float s = -3.402823466e38f;
        if (ok) {
            s = 0.f;
            #pragma unroll
            for (int d = 0; d < DH; d++) s += qs[i][d] * ks[j][d];
        }
        sc[i][j] = s;
    }
    __syncthreads();
    if (threadIdx.x < Jm) {
        int i = threadIdx.x;
        float mx = -3.402823466e38f;
        #pragma unroll
        for (int j = 0; j < Jm; j++) mx = fmaxf(mx, sc[i][j]);
        float e[Jm]; float sum = 0.f;
        #pragma unroll
        for (int j = 0; j < Jm; j++) { e[j] = expf(sc[i][j] - mx); sum += e[j]; }
        float inv = 1.f / sum;
        #pragma unroll
        for (int j = 0; j < Jm; j++) sc[i][j] = e[j] * inv;
    }
    __syncthreads();
    for (int idx = threadIdx.x; idx < Jm * DH; idx += blockDim.x) {
        int i = idx >> 5, d = idx & 31;
        float a0 = 0.f;
        #pragma unroll
        for (int j = 0; j < Jm; j++) a0 += sc[i][j] * vs[j][d];
        o[((size_t)(n * Jm + i)) * Hdim + head * DH + d] = __float2bfloat16(a0);
    }
}

// ---------------- launcher ----------------
extern "C" void kernel_launch(void* const* d_in, const int* in_sizes, int n_in,
                              void* d_out, int out_size)
{
    (void)in_sizes; (void)n_in; (void)out_size;
    const float* act   = (const float*)d_in[0];
    const unsigned char* smk = (const unsigned char*)d_in[1];
    const unsigned char* hmk = (const unsigned char*)d_in[2];
    const unsigned char* gmk = (const unsigned char*)d_in[3];
    const int*   m_idx = (const int*)d_in[6];
    const float* Ws    = (const float*)d_in[7];
    const float* bs    = (const float*)d_in[8];
    const float* Wh    = (const float*)d_in[9];
    const float* bh    = (const float*)d_in[10];
    const float* Wg    = (const float*)d_in[11];
    const float* Wact  = (const float*)d_in[12];
    const float* pos   = (const float*)d_in[13];
    const float* ln1_s = (const float*)d_in[14];
    const float* ln1_b = (const float*)d_in[15];
    const float* Wqkv  = (const float*)d_in[16];
    const float* bqkv  = (const float*)d_in[17];
    const float* loraA = (const float*)d_in[18];
    const float* loraB = (const float*)d_in[19];
    const float* Wo    = (const float*)d_in[20];
    const float* bo    = (const float*)d_in[21];
    const float* ln2_s = (const float*)d_in[22];
    const float* ln2_b = (const float*)d_in[23];
    const float* W1    = (const float*)d_in[24];
    const float* b1    = (const float*)d_in[25];
    const float* W2    = (const float*)d_in[26];
    const float* b2    = (const float*)d_in[27];
    const float* g1    = (const float*)d_in[28];
    const float* g2    = (const float*)d_in[29];
    const float* lnf_s = (const float*)d_in[30];
    const float* lnf_b = (const float*)d_in[31];
    float* out = (float*)d_out;

    float *x, *tmp; __nv_bfloat16 *h, *qkv, *ob, *midb, *wt; int *cat;
    cudaGetSymbolAddress((void**)&x,    g_x);
    cudaGetSymbolAddress((void**)&h,    g_h);
    cudaGetSymbolAddress((void**)&qkv,  g_qkv);
    cudaGetSymbolAddress((void**)&ob,   g_o);
    cudaGetSymbolAddress((void**)&midb, g_midb);
    cudaGetSymbolAddress((void**)&tmp,  g_tmp);
    cudaGetSymbolAddress((void**)&wt,   g_wt);
    cudaGetSymbolAddress((void**)&cat,  g_cat);

    cudaFuncSetAttribute((const void*)hmma256_kernel<1, __nv_bfloat16>, cudaFuncAttributeMaxDynamicSharedMemorySize, GSMEM);
    cudaFuncSetAttribute((const void*)hmma256_kernel<3, __nv_bfloat16>, cudaFuncAttributeMaxDynamicSharedMemorySize, GSMEM);
    cudaFuncSetAttribute((const void*)hmma256_kernel<4, __nv_bfloat16>, cudaFuncAttributeMaxDynamicSharedMemorySize, GSMEM);
    cudaFuncSetAttribute((const void*)hmma256_kernel<4, float>,         cudaFuncAttributeMaxDynamicSharedMemorySize, GSMEM);

    detect_cat_kernel<<<1, 256>>>(smk, hmk, gmk, cat);

    const size_t OFF_QKV = 0, OFF_WO = 196608, OFF_W1 = 262144, OFF_W2 = 524288, LSZ = 786432;
    transpose_bf16_kernel<<<dim3(H3 / 32, Hdim / 32, Lnum), dim3(32, 8)>>>(
        Wqkv, wt + OFF_QKV, Hdim, H3, (size_t)Hdim * H3, LSZ);
    transpose_bf16_kernel<<<dim3(Hdim / 32, Hdim / 32, Lnum), dim3(32, 8)>>>(
        Wo, wt + OFF_WO, Hdim, Hdim, (size_t)Hdim * Hdim, LSZ);
    transpose_bf16_kernel<<<dim3(H4 / 32, Hdim / 32, Lnum), dim3(32, 8)>>>(
        W1, wt + OFF_W1, Hdim, H4, (size_t)Hdim * H4, LSZ);
    transpose_bf16_kernel<<<dim3(Hdim / 32, H4 / 32, Lnum), dim3(32, 8)>>>(
        W2, wt + OFF_W2, H4, Hdim, (size_t)H4 * Hdim, LSZ);

    embed_kernel<<<NTOK, 256>>>(act, m_idx, cat, Ws, bs, Wh, bh, Wg, Wact, pos, x);
    ln_warp_kernel<__nv_bfloat16><<<NTOK / 8, 256>>>(x, h, ln1_s, ln1_b);

    const dim3 gQKV(H3 / 256, NTOK / 128), gWO(1, NTOK / 128), gW1(H4 / 256, NTOK / 128), gW2(1, NTOK / 128);

    for (int l = 0; l < Lnum; l++) {
        lora_tmp_kernel<<<NTOK / 8, 256>>>(h, loraA + (size_t)l * Mnum * Hdim * RANKv, m_idx, tmp);
        // qkv = h @ WqkvT + bqkv + lora
        hmma256_kernel<3, __nv_bfloat16><<<gQKV, 512, GSMEM>>>(
            h, wt + l * LSZ + OFF_QKV, nullptr, qkv, bqkv + l * H3, nullptr,
            tmp, loraB + (size_t)l * Mnum * RANKv * H3, m_idx,
            nullptr, nullptr, (__nv_bfloat16*)nullptr, Hdim, H3);
        attn_kernel<<<dim3(NSEQ, HEADS), 128>>>(qkv, ob, m_idx);
        // x += g1*(o @ WoT + bo); h = LN2(x)
        hmma256_kernel<4, __nv_bfloat16><<<gWO, 512, GSMEM>>>(
            ob, wt + l * LSZ + OFF_WO, x, nullptr, bo + l * Hdim, g1 + l * Hdim,
            nullptr, nullptr, nullptr,
            ln2_s + l * Hdim, ln2_b + l * Hdim, h, Hdim, Hdim);
        // midb = gelu(h @ W1T + b1)
        hmma256_kernel<1, __nv_bfloat16><<<gW1, 512, GSMEM>>>(
            h, wt + l * LSZ + OFF_W1, nullptr, midb, b1 + l * H4, nullptr,
            nullptr, nullptr, nullptr,
            nullptr, nullptr, (__nv_bfloat16*)nullptr, Hdim, H4);
        // x += g2*(midb @ W2T + b2); h = LN1[l+1](x)  (or out = LNf(x))
        if (l < Lnum - 1) {
            hmma256_kernel<4, __nv_bfloat16><<<gW2, 512, GSMEM>>>(
                midb, wt + l * LSZ + OFF_W2, x, nullptr, b2 + l * Hdim, g2 + l * Hdim,
                nullptr, nullptr, nullptr,
                ln1_s + (l + 1) * Hdim, ln1_b + (l + 1) * Hdim, h, H4, Hdim);
        } else {
            hmma256_kernel<4, float><<<gW2, 512, GSMEM>>>(
                midb, wt + l * LSZ + OFF_W2, x, nullptr, b2 + l * Hdim, g2 + l * Hdim,
                nullptr, nullptr, nullptr,
                lnf_s, lnf_b, out, H4, Hdim);
        }
    }
}

// round 7
// speedup vs baseline: 1.0862x; 1.0862x over previous
#include <cuda_runtime.h>
#include <cuda_bf16.h>
#include <math.h>
#include <stdint.h>

// ---------------- problem constants ----------------
#define NTOK  49152
#define NSEQ  2048
#define Bdim  16
#define Tdim  128
#define Jm    24
#define Hdim  256
#define H3    768
#define H4    1024
#define Lnum  4
#define Mnum  12
#define RANKv 8
#define HEADS 8
#define DH    32
#define TOKPB 3072

__constant__ int c_nj[Mnum] = {8,10,12,14,16,18,20,22,24,9,13,17};

// ---------------- scratch ----------------
__device__ float         g_x   [(size_t)NTOK * Hdim];
__device__ __nv_bfloat16 g_h   [(size_t)NTOK * Hdim];
__device__ __nv_bfloat16 g_qkv [(size_t)NTOK * H3 ];
__device__ __nv_bfloat16 g_o   [(size_t)NTOK * Hdim];
__device__ __nv_bfloat16 g_midb[(size_t)NTOK * H4 ];
__device__ float         g_tmp [(size_t)NTOK * RANKv];
__device__ __nv_bfloat16 g_wt  [(size_t)Lnum * 786432];
__device__ int           g_cat [Bdim * Jm];

// ---------------- helpers ----------------
__device__ __forceinline__ uint32_t smem_u32(const void* p) {
    uint32_t a;
    asm("{ .reg .u64 t; cvta.to.shared.u64 t, %1; cvt.u32.u64 %0, t; }" : "=r"(a) : "l"(p));
    return a;
}
__device__ __forceinline__ void cp16(uint32_t dst, const void* src) {
    asm volatile("cp.async.cg.shared.global [%0], [%1], 16;" :: "r"(dst), "l"(src));
}
__device__ __forceinline__ void cp_commit() { asm volatile("cp.async.commit_group;"); }
__device__ __forceinline__ void ldm_x4(uint32_t& r0, uint32_t& r1, uint32_t& r2, uint32_t& r3, uint32_t a) {
    asm volatile("ldmatrix.sync.aligned.m8n8.x4.shared.b16 {%0,%1,%2,%3}, [%4];"
                 : "=r"(r0), "=r"(r1), "=r"(r2), "=r"(r3) : "r"(a));
}
__device__ __forceinline__ void mma16816(float* c, const uint32_t* a, const uint32_t* b) {
    asm volatile("mma.sync.aligned.m16n8k16.row.col.f32.bf16.bf16.f32 "
                 "{%0,%1,%2,%3},{%4,%5,%6,%7},{%8,%9},{%0,%1,%2,%3};"
                 : "+f"(c[0]), "+f"(c[1]), "+f"(c[2]), "+f"(c[3])
                 : "r"(a[0]), "r"(a[1]), "r"(a[2]), "r"(a[3]), "r"(b[0]), "r"(b[1]));
}
__device__ __forceinline__ uint32_t pack2bf(float x, float y) {
    __nv_bfloat162 h = __floats2bfloat162_rn(x, y);
    return *reinterpret_cast<uint32_t*>(&h);
}
__device__ __forceinline__ float gelu_tanh(float x) {
    float x3 = x * x * x;
    return 0.5f * x * (1.f + tanhf(0.7978845608028654f * (x + 0.044715f * x3)));
}

// ================= kernel 1: 128x128 HMMA GEMM (round-5 proven) =================
// 8 warps (2x4), warp tile 64x32, K-chunk 64, 3-stage cp.async, XOR swizzle.
// EPI 1: Cb = bf16(gelu(acc+bias));  EPI 3: Cb = bf16(acc+bias+lora)
#define TILE2  16384
#define NSTG   3
#define GSMEM  (NSTG * 2 * TILE2)    // 98304

template<int EPI>
__global__ void __launch_bounds__(256)
hmma_gemm_kernel(const __nv_bfloat16* __restrict__ A, const __nv_bfloat16* __restrict__ Bt,
                 __nv_bfloat16* __restrict__ Cb,
                 const float* __restrict__ bias,
                 const float* __restrict__ ltmp, const float* __restrict__ lB,
                 const int* __restrict__ midx,
                 int K, int N)
{
    extern __shared__ char dynsm[];

    int tid = threadIdx.x, lane = tid & 31, wid = tid >> 5;
    int wm = wid & 1, wn = wid >> 1;
    int brow = blockIdx.y * 128, bcol = blockIdx.x * 128;

    float acc[4][4][4];
    #pragma unroll
    for (int i = 0; i < 4; i++)
        #pragma unroll
        for (int j = 0; j < 4; j++)
            #pragma unroll
            for (int q = 0; q < 4; q++) acc[i][j][q] = 0.f;

    int nch = K >> 6;

    auto load_tiles = [&](int ch, int stage) {
        const __nv_bfloat16* As = A + (size_t)brow * K + ch * 64;
        const __nv_bfloat16* Bs = Bt + (size_t)bcol * K + ch * 64;
        uint32_t da = smem_u32(dynsm + (stage * 2 + 0) * TILE2);
        uint32_t db = smem_u32(dynsm + (stage * 2 + 1) * TILE2);
        #pragma unroll
        for (int hh = 0; hh < 4; hh++) {
            int cid = tid + hh * 256;
            int row = cid >> 3, cc = cid & 7;
            uint32_t so = (uint32_t)(row * 128 + ((cc ^ (row & 7)) * 16));
            cp16(da + so, As + (size_t)row * K + cc * 8);
            cp16(db + so, Bs + (size_t)row * K + cc * 8);
        }
        cp_commit();
    };

    load_tiles(0, 0);
    load_tiles(1, 1);

    for (int ch = 0; ch < nch; ch++) {
        asm volatile("cp.async.wait_group 1;");
        __syncthreads();

        int st = ch % NSTG;
        uint32_t sa = smem_u32(dynsm + (st * 2 + 0) * TILE2);
        uint32_t sb = smem_u32(dynsm + (st * 2 + 1) * TILE2);
        int rsel = lane & 15, ksel = lane >> 4;

        #pragma unroll
        for (int ks = 0; ks < 4; ks++) {
            int chunk = ks * 2 + ksel;
            uint32_t a[4][4];
            #pragma unroll
            for (int mf = 0; mf < 4; mf++) {
                int ar = wm * 64 + mf * 16 + rsel;
                ldm_x4(a[mf][0], a[mf][1], a[mf][2], a[mf][3],
                       sa + (uint32_t)(ar * 128 + ((chunk ^ (ar & 7)) * 16)));
            }
            uint32_t b[4][2];
            #pragma unroll
            for (int nf2 = 0; nf2 < 2; nf2++) {
                uint32_t r0, r1, r2, r3;
                int br = wn * 32 + nf2 * 16 + rsel;
                ldm_x4(r0, r1, r2, r3,
                       sb + (uint32_t)(br * 128 + ((chunk ^ (br & 7)) * 16)));
                b[nf2 * 2 + 0][0] = r0; b[nf2 * 2 + 0][1] = r2;
                b[nf2 * 2 + 1][0] = r1; b[nf2 * 2 + 1][1] = r3;
            }
            #pragma unroll
            for (int mf = 0; mf < 4; mf++)
                #pragma unroll
                for (int nf = 0; nf < 4; nf++)
                    mma16816(acc[mf][nf], a[mf], b[nf]);
        }

        if (ch + 2 < nch) load_tiles(ch + 2, (ch + 2) % NSTG);
        else              cp_commit();
    }

    float* lb_s  = (float*)dynsm;
    float* tmp_s = (float*)(dynsm + 4096);
    if (EPI == 3) {
        __syncthreads();
        int m = midx[brow / TOKPB];
        #pragma unroll
        for (int hh = 0; hh < 4; hh++) {
            int i = tid + hh * 256;
            int q = i >> 7, c = i & 127;
            lb_s[q * 128 + c] = lB[((size_t)m * RANKv + q) * N + bcol + c];
            int r = i >> 3, q2 = i & 7;
            tmp_s[r * 9 + q2] = ltmp[(size_t)(brow + r) * RANKv + q2];
        }
        __syncthreads();
    }

    int g = lane >> 2, tg = lane & 3;
    #pragma unroll
    for (int mf = 0; mf < 4; mf++) {
        int rl = wm * 64 + mf * 16 + g;
        int r0 = brow + rl;
        float t0[8], t1[8];
        if (EPI == 3) {
            #pragma unroll
            for (int q = 0; q < 8; q++) { t0[q] = tmp_s[rl * 9 + q]; t1[q] = tmp_s[(rl + 8) * 9 + q]; }
        }
        #pragma unroll
        for (int nf = 0; nf < 4; nf++) {
            int cl  = wn * 32 + nf * 8 + tg * 2;
            int col = bcol + cl;
            float b0 = bias[col], b1 = bias[col + 1];
            float v0 = acc[mf][nf][0] + b0, v1 = acc[mf][nf][1] + b1;
            float v2 = acc[mf][nf][2] + b0, v3 = acc[mf][nf][3] + b1;
            if (EPI == 1) {
                *(uint32_t*)(Cb + (size_t)r0 * N + col)       = pack2bf(gelu_tanh(v0), gelu_tanh(v1));
                *(uint32_t*)(Cb + (size_t)(r0 + 8) * N + col) = pack2bf(gelu_tanh(v2), gelu_tanh(v3));
            } else {
                float a00 = 0.f, a01 = 0.f, a10 = 0.f, a11 = 0.f;
                #pragma unroll
                for (int q = 0; q < 8; q++) {
                    float w0 = lb_s[q * 128 + cl], w1 = lb_s[q * 128 + cl + 1];
                    a00 += t0[q] * w0; a01 += t0[q] * w1;
                    a10 += t1[q] * w0; a11 += t1[q] * w1;
                }
                *(uint32_t*)(Cb + (size_t)r0 * N + col)       = pack2bf(v0 + a00, v1 + a01);
                *(uint32_t*)(Cb + (size_t)(r0 + 8) * N + col) = pack2bf(v2 + a10, v3 + a11);
            }
        }
    }
}

// ================= kernel 2: 64x256 HMMA GEMM + residual + fused LayerNorm =================
// 8 warps (2x4), warp tile 32x64, K-chunk 64, 2-stage, 80KB smem -> 2 CTAs/SM.
// x += gsc*(acc+bias); then LN over the CTA's 64 full 256-col rows -> Hout (bf16 or f32).
#define TA64   8192                  // 64 x 128B
#define TB256  32768                 // 256 x 128B
#define STG64  (TA64 + TB256)        // 40960
#define GSMEM2 (2 * STG64)           // 81920

template<typename TO>
__global__ void __launch_bounds__(256, 2)
hmma_ln_kernel(const __nv_bfloat16* __restrict__ A, const __nv_bfloat16* __restrict__ Bt,
               float* __restrict__ C,
               const float* __restrict__ bias, const float* __restrict__ gsc,
               const float* __restrict__ lnS, const float* __restrict__ lnB,
               TO* __restrict__ Hout,
               int K)
{
    extern __shared__ char dynsm[];
    const int N = 256;

    int tid = threadIdx.x, lane = tid & 31, wid = tid >> 5;
    int wm = wid & 1, wn = wid >> 1;
    int brow = blockIdx.y * 64;

    float acc[2][8][4];
    #pragma unroll
    for (int i = 0; i < 2; i++)
        #pragma unroll
        for (int j = 0; j < 8; j++)
            #pragma unroll
            for (int q = 0; q < 4; q++) acc[i][j][q] = 0.f;

    int nch = K >> 6;

    auto load_tiles = [&](int ch, int stage) {
        const __nv_bfloat16* As = A + (size_t)brow * K + ch * 64;
        const __nv_bfloat16* Bs = Bt + ch * 64;
        uint32_t da = smem_u32(dynsm + stage * STG64);
        uint32_t db = da + TA64;
        #pragma unroll
        for (int hh = 0; hh < 2; hh++) {
            int cid = tid + hh * 256;          // 512 A-chunks
            int row = cid >> 3, cc = cid & 7;
            cp16(da + (uint32_t)(row * 128 + ((cc ^ (row & 7)) * 16)),
                 As + (size_t)row * K + cc * 8);
        }
        #pragma unroll
        for (int hh = 0; hh < 8; hh++) {
            int cid = tid + hh * 256;          // 2048 B-chunks
            int row = cid >> 3, cc = cid & 7;
            cp16(db + (uint32_t)(row * 128 + ((cc ^ (row & 7)) * 16)),
                 Bs + (size_t)row * K + cc * 8);
        }
        cp_commit();
    };

    load_tiles(0, 0);

    for (int ch = 0; ch < nch; ch++) {
        if (ch + 1 < nch) {
            load_tiles(ch + 1, (ch + 1) & 1);
            asm volatile("cp.async.wait_group 1;");
        } else {
            asm volatile("cp.async.wait_group 0;");
        }
        __syncthreads();

        int st = ch & 1;
        uint32_t sa = smem_u32(dynsm + st * STG64);
        uint32_t sb = sa + TA64;
        int rsel = lane & 15, ksel = lane >> 4;

        #pragma unroll
        for (int ks = 0; ks < 4; ks++) {
            int chunk = ks * 2 + ksel;
            uint32_t a[2][4];
            #pragma unroll
            for (int mf = 0; mf < 2; mf++) {
                int ar = wm * 32 + mf * 16 + rsel;
                ldm_x4(a[mf][0], a[mf][1], a[mf][2], a[mf][3],
                       sa + (uint32_t)(ar * 128 + ((chunk ^ (ar & 7)) * 16)));
            }
            uint32_t b[8][2];
            #pragma unroll
            for (int nf2 = 0; nf2 < 4; nf2++) {
                uint32_t r0, r1, r2, r3;
                int br = wn * 64 + nf2 * 16 + rsel;
                ldm_x4(r0, r1, r2, r3,
                       sb + (uint32_t)(br * 128 + ((chunk ^ (br & 7)) * 16)));
                b[nf2 * 2 + 0][0] = r0; b[nf2 * 2 + 0][1] = r2;
                b[nf2 * 2 + 1][0] = r1; b[nf2 * 2 + 1][1] = r3;
            }
            #pragma unroll
            for (int mf = 0; mf < 2; mf++)
                #pragma unroll
                for (int nf = 0; nf < 8; nf++)
                    mma16816(acc[mf][nf], a[mf], b[nf]);
        }
        __syncthreads();
    }

    int g = lane >> 2, tg = lane & 3;

    // residual rmw; keep updated x in acc
    #pragma unroll
    for (int mf = 0; mf < 2; mf++) {
        int r0 = brow + wm * 32 + mf * 16 + g;
        #pragma unroll
        for (int nf = 0; nf < 8; nf++) {
            int col = wn * 64 + nf * 8 + tg * 2;
            float b0 = bias[col], b1 = bias[col + 1];
            float s0 = gsc[col],  s1 = gsc[col + 1];
            float2 o0 = *(float2*)(C + (size_t)r0 * N + col);
            float2 o1 = *(float2*)(C + (size_t)(r0 + 8) * N + col);
            o0.x += s0 * (acc[mf][nf][0] + b0); o0.y += s1 * (acc[mf][nf][1] + b1);
            o1.x += s0 * (acc[mf][nf][2] + b0); o1.y += s1 * (acc[mf][nf][3] + b1);
            *(float2*)(C + (size_t)r0 * N + col)       = o0;
            *(float2*)(C + (size_t)(r0 + 8) * N + col) = o1;
            acc[mf][nf][0] = o0.x; acc[mf][nf][1] = o0.y;
            acc[mf][nf][2] = o1.x; acc[mf][nf][3] = o1.y;
        }
    }

    // fused LayerNorm over 64 full rows
    float* ssum = (float*)dynsm;     // [64][4]
    float* ssq  = ssum + 256;        // [64][4]
    float* smu  = ssq + 256;         // [64]
    float* srs  = smu + 64;          // [64]
    __syncthreads();

    #pragma unroll
    for (int mf = 0; mf < 2; mf++) {
        #pragma unroll
        for (int half = 0; half < 2; half++) {
            float ps = 0.f, pq = 0.f;
            #pragma unroll
            for (int nf = 0; nf < 8; nf++) {
                float v0 = acc[mf][nf][half * 2 + 0];
                float v1 = acc[mf][nf][half * 2 + 1];
                ps += v0 + v1;
                pq += v0 * v0 + v1 * v1;
            }
            ps += __shfl_xor_sync(0xffffffffu, ps, 1);
            pq += __shfl_xor_sync(0xffffffffu, pq, 1);
            ps += __shfl_xor_sync(0xffffffffu, ps, 2);
            pq += __shfl_xor_sync(0xffffffffu, pq, 2);
            if (tg == 0) {
                int rl = wm * 32 + mf * 16 + half * 8 + g;
                ssum[rl * 4 + wn] = ps;
                ssq [rl * 4 + wn] = pq;
            }
        }
    }
    __syncthreads();
    if (tid < 64) {
        float s = ssum[tid * 4] + ssum[tid * 4 + 1] + ssum[tid * 4 + 2] + ssum[tid * 4 + 3];
        float q = ssq [tid * 4] + ssq [tid * 4 + 1] + ssq [tid * 4 + 2] + ssq [tid * 4 + 3];
        float mu = s * (1.f / 256.f);
        float var = fmaxf(q * (1.f / 256.f) - mu * mu, 0.f);
        smu[tid] = mu;
        srs[tid] = rsqrtf(var + 1e-5f);
    }
    __syncthreads();

    #pragma unroll
    for (int mf = 0; mf < 2; mf++) {
        int rl = wm * 32 + mf * 16 + g;
        float mu0 = smu[rl],     rs0 = srs[rl];
        float mu1 = smu[rl + 8], rs1 = srs[rl + 8];
        int r0 = brow + rl;
        #pragma unroll
        for (int nf = 0; nf < 8; nf++) {
            int col = wn * 64 + nf * 8 + tg * 2;
            float sc0 = lnS[col], sc1 = lnS[col + 1];
            float bi0 = lnB[col], bi1 = lnB[col + 1];
            float h0 = (acc[mf][nf][0] - mu0) * rs0 * sc0 + bi0;
            float h1 = (acc[mf][nf][1] - mu0) * rs0 * sc1 + bi1;
            float h2 = (acc[mf][nf][2] - mu1) * rs1 * sc0 + bi0;
            float h3 = (acc[mf][nf][3] - mu1) * rs1 * sc1 + bi1;
            if constexpr (sizeof(TO) == 2) {
                *(uint32_t*)((__nv_bfloat16*)Hout + (size_t)r0 * N + col)       = pack2bf(h0, h1);
                *(uint32_t*)((__nv_bfloat16*)Hout + (size_t)(r0 + 8) * N + col) = pack2bf(h2, h3);
            } else {
                *(float2*)((float*)Hout + (size_t)r0 * N + col)       = make_float2(h0, h1);
                *(float2*)((float*)Hout + (size_t)(r0 + 8) * N + col) = make_float2(h2, h3);
            }
        }
    }
}

// ---------------- weight transpose-convert ----------------
__global__ void transpose_bf16_kernel(const float* __restrict__ src,
                                      __nv_bfloat16* __restrict__ dst, int K, int N,
                                      size_t sstride, size_t dstride)
{
    src += blockIdx.z * sstride;
    dst += blockIdx.z * dstride;
    __shared__ float t[32][33];
    int kb = blockIdx.y * 32, nb = blockIdx.x * 32;
    int x = threadIdx.x, y = threadIdx.y;
    #pragma unroll
    for (int i = 0; i < 32; i += 8)
        t[y + i][x] = src[(size_t)(kb + y + i) * N + nb + x];
    __syncthreads();
    #pragma unroll
    for (int i = 0; i < 32; i += 8)
        dst[(size_t)(nb + y + i) * K + kb + x] = __float2bfloat16(t[x][y + i]);
}

// ---------------- mask-format detection + category ----------------
__global__ void detect_cat_kernel(const unsigned char* __restrict__ sm,
                                  const unsigned char* __restrict__ hm,
                                  const unsigned char* __restrict__ gm,
                                  int* __restrict__ cat)
{
    __shared__ int offbyte, i32bad, f32bad, f32one;
    __shared__ int fmt_s;
    if (threadIdx.x == 0) { offbyte = 0; i32bad = 0; f32bad = 0; f32one = 0; }
    __syncthreads();
    const unsigned char* bufs[3] = {sm, hm, gm};
    for (int bi = 0; bi < 3; bi++) {
        const unsigned char* p = bufs[bi];
        for (int i = threadIdx.x; i < NTOK; i += blockDim.x)
            if ((i & 3) != 0 && p[i] != 0) atomicOr(&offbyte, 1);
        const int*   pi = (const int*)p;
        const float* pf = (const float*)p;
        for (int i = threadIdx.x; i < NTOK / 4; i += blockDim.x) {
            int iv = pi[i]; float fv = pf[i];
            if (iv != 0 && iv != 1)     atomicOr(&i32bad, 1);
            if (fv != 0.f && fv != 1.f) atomicOr(&f32bad, 1);
            if (fv == 1.f)              atomicOr(&f32one, 1);
        }
    }
    __syncthreads();
    if (threadIdx.x == 0) {
        int fmt;
        if (!offbyte && !i32bad)    fmt = 1;
        else if (!f32bad && f32one) fmt = 2;
        else                        fmt = 0;
        fmt_s = fmt;
    }
    __syncthreads();
    int fmt = fmt_s;
    for (int idx = threadIdx.x; idx < Bdim * Jm; idx += blockDim.x) {
        int b = idx / Jm, j = idx % Jm;
        int e = b * (Tdim * Jm) + j;
        bool sv, hv, gv;
        if (fmt == 0)      { sv = sm[e] != 0; hv = hm[e] != 0; gv = gm[e] != 0; }
        else if (fmt == 1) { sv = ((const int*)sm)[e] != 0; hv = ((const int*)hm)[e] != 0; gv = ((const int*)gm)[e] != 0; }
        else               { sv = ((const float*)sm)[e] != 0.f; hv = ((const float*)hm)[e] != 0.f; gv = ((const float*)gm)[e] != 0.f; }
        cat[idx] = sv ? 0 : (hv ? 1 : (gv ? 2 : 3));
    }
}

// ---------------- embedding ----------------
__global__ void embed_kernel(const float* __restrict__ act,
                             const int* __restrict__ m_idx, const int* __restrict__ cat,
                             const float* __restrict__ Ws, const float* __restrict__ bs,
                             const float* __restrict__ Wh, const float* __restrict__ bh,
                             const float* __restrict__ Wg, const float* __restrict__ Wact,
                             const float* __restrict__ pos, float* __restrict__ x)
{
    int token = blockIdx.x;
    int c = threadIdx.x;
    int j = token % Jm;
    int b = token / TOKPB;
    int m = m_idx[b];
    int ct = cat[b * Jm + j];
    float a = act[token];
    float e;
    if      (ct == 0) e = a * Ws[c] + bs[c];
    else if (ct == 1) e = a * Wh[c] + bh[c];
    else if (ct == 2) e = a * Wg[m * Hdim + c];
    else              e = 0.f;
    if (ct != 3) e += Wact[c];
    e += pos[((size_t)m * Jm + j) * Hdim + c];
    x[(size_t)token * Hdim + c] = e;
}

// ---------------- standalone layernorm (layer-0 entry only) ----------------
__global__ void ln_warp_kernel(const float* __restrict__ in, __nv_bfloat16* __restrict__ out,
                               const float* __restrict__ sc, const float* __restrict__ bi)
{
    int token = blockIdx.x * 8 + (threadIdx.x >> 5);
    int lane = threadIdx.x & 31;
    const float4* p = (const float4*)(in + (size_t)token * Hdim);
    float4 a = p[lane], b = p[lane + 32];
    float s = a.x + a.y + a.z + a.w + b.x + b.y + b.z + b.w;
    #pragma unroll
    for (int o = 16; o > 0; o >>= 1) s += __shfl_xor_sync(0xffffffffu, s, o);
    float mu = s * (1.f / Hdim);
    a.x -= mu; a.y -= mu; a.z -= mu; a.w -= mu;
    b.x -= mu; b.y -= mu; b.z -= mu; b.w -= mu;
    float v = a.x*a.x + a.y*a.y + a.z*a.z + a.w*a.w + b.x*b.x + b.y*b.y + b.z*b.z + b.w*b.w;
    #pragma unroll
    for (int o = 16; o > 0; o >>= 1) v += __shfl_xor_sync(0xffffffffu, v, o);
    float r = rsqrtf(v * (1.f / Hdim) + 1e-5f);
    const float4* s4 = (const float4*)sc;
    const float4* b4 = (const float4*)bi;
    float4 sa = s4[lane], sb = s4[lane + 32], ba = b4[lane], bb = b4[lane + 32];
    float o0 = a.x * r * sa.x + ba.x, o1 = a.y * r * sa.y + ba.y;
    float o2 = a.z * r * sa.z + ba.z, o3 = a.w * r * sa.w + ba.w;
    float o4 = b.x * r * sb.x + bb.x, o5 = b.y * r * sb.y + bb.y;
    float o6 = b.z * r * sb.z + bb.z, o7 = b.w * r * sb.w + bb.w;
    uint2* q = (uint2*)(out + (size_t)token * Hdim);
    q[lane]      = make_uint2(pack2bf(o0, o1), pack2bf(o2, o3));
    q[lane + 32] = make_uint2(pack2bf(o4, o5), pack2bf(o6, o7));
}

// ---------------- LoRA stage 1 ----------------
__global__ void lora_tmp_kernel(const __nv_bfloat16* __restrict__ h,
                                const float* __restrict__ lA,
                                const int* __restrict__ m_idx,
                                float* __restrict__ tmp)
{
    int token = blockIdx.x * 8 + (threadIdx.x >> 5);
    int lane = threadIdx.x & 31;
    int m = m_idx[token / TOKPB];
    const float* A = lA + (size_t)m * Hdim * RANKv;
    float s[8] = {0.f, 0.f, 0.f, 0.f, 0.f, 0.f, 0.f, 0.f};
    #pragma unroll
    for (int d0 = 0; d0 < Hdim; d0 += 32) {
        int d = d0 + lane;
        float hv = __bfloat162float(h[(size_t)token * Hdim + d]);
        const float4* ap = (const float4*)(A + (size_t)d * RANKv);
        float4 a0 = ap[0], a1 = ap[1];
        s[0] += hv * a0.x; s[1] += hv * a0.y; s[2] += hv * a0.z; s[3] += hv * a0.w;
        s[4] += hv * a1.x; s[5] += hv * a1.y; s[6] += hv * a1.z; s[7] += hv * a1.w;
    }
    #pragma unroll
    for (int r = 0; r < 8; r++)
        #pragma unroll
        for (int o = 16; o > 0; o >>= 1) s[r] += __shfl_xor_sync(0xffffffffu, s[r], o);
    if (lane < 8) tmp[(size_t)token * RANKv + lane] = s[lane];
}

// ---------------- attention ----------------
__global__ void attn_kernel(const __nv_bfloat16* __restrict__ qkv, __nv_bfloat16* __restrict__ o,
                            const int* __restrict__ m_idx)
{
    __shared__ float qs[Jm][DH + 1];
    __shared__ float ks[Jm][DH + 1];
    __shared__ float vs[Jm][DH + 1];
    __shared__ float sc[Jm][Jm + 1];
    int n = blockIdx.x, head = blockIdx.y;
    int b = n >> 7;
    int nj = c_nj[m_idx[b]];
    const float scale = 0.17677669529663687f;
    for (int idx = threadIdx.x; idx < Jm * DH; idx += blockDim.x) {
        int j = idx >> 5, d = idx & 31;
        size_t base = ((size_t)(n * Jm + j)) * H3 + head * DH + d;
        qs[j][d] = __bfloat162float(qkv[base]) * scale;
        ks[j][d] = __bfloat162float(qkv[base + Hdim]);
        vs[j][d] = __bfloat162float(qkv[base + 2 * Hdim]);
    }
    __syncthreads();
    for (int idx = threadIdx.x; idx < Jm * Jm; idx += blockDim.x) {
        int i = idx / Jm, j = idx % Jm;
        bool ok = (i < nj && j < nj) || (i == j);
        float s = -3.402823466e38f;
        if (ok) {
            s = 0.f;
            #pragma unroll
            for (int d = 0; d < DH; d++) s += qs[i][d] * ks[j][d];
        }
        sc[i][j] = s;
    }
    __syncthreads();
    if (threadIdx.x < Jm) {
        int i = threadIdx.x;
        float mx = -3.402823466e38f;
        #pragma unroll
        for (int j = 0; j < Jm; j++) mx = fmaxf(mx, sc[i][j]);
        float e[Jm]; float sum = 0.f;
        #pragma unroll
        for (int j = 0; j < Jm; j++) { e[j] = expf(sc[i][j] - mx); sum += e[j]; }
        float inv = 1.f / sum;
        #pragma unroll
        for (int j = 0; j < Jm; j++) sc[i][j] = e[j] * inv;
    }
    __syncthreads();
    for (int idx = threadIdx.x; idx < Jm * DH; idx += blockDim.x) {
        int i = idx >> 5, d = idx & 31;
        float a0 = 0.f;
        #pragma unroll
        for (int j = 0; j < Jm; j++) a0 += sc[i][j] * vs[j][d];
        o[((size_t)(n * Jm + i)) * Hdim + head * DH + d] = __float2bfloat16(a0);
    }
}

// ---------------- launcher ----------------
extern "C" void kernel_launch(void* const* d_in, const int* in_sizes, int n_in,
                              void* d_out, int out_size)
{
    (void)in_sizes; (void)n_in; (void)out_size;
    const float* act   = (const float*)d_in[0];
    const unsigned char* smk = (const unsigned char*)d_in[1];
    const unsigned char* hmk = (const unsigned char*)d_in[2];
    const unsigned char* gmk = (const unsigned char*)d_in[3];
    const int*   m_idx = (const int*)d_in[6];
    const float* Ws    = (const float*)d_in[7];
    const float* bs    = (const float*)d_in[8];
    const float* Wh    = (const float*)d_in[9];
    const float* bh    = (const float*)d_in[10];
    const float* Wg    = (const float*)d_in[11];
    const float* Wact  = (const float*)d_in[12];
    const float* pos   = (const float*)d_in[13];
    const float* ln1_s = (const float*)d_in[14];
    const float* ln1_b = (const float*)d_in[15];
    const float* Wqkv  = (const float*)d_in[16];
    const float* bqkv  = (const float*)d_in[17];
    const float* loraA = (const float*)d_in[18];
    const float* loraB = (const float*)d_in[19];
    const float* Wo    = (const float*)d_in[20];
    const float* bo    = (const float*)d_in[21];
    const float* ln2_s = (const float*)d_in[22];
    const float* ln2_b = (const float*)d_in[23];
    const float* W1    = (const float*)d_in[24];
    const float* b1    = (const float*)d_in[25];
    const float* W2    = (const float*)d_in[26];
    const float* b2    = (const float*)d_in[27];
    const float* g1    = (const float*)d_in[28];
    const float* g2    = (const float*)d_in[29];
    const float* lnf_s = (const float*)d_in[30];
    const float* lnf_b = (const float*)d_in[31];
    float* out = (float*)d_out;

    float *x, *tmp; __nv_bfloat16 *h, *qkv, *ob, *midb, *wt; int *cat;
    cudaGetSymbolAddress((void**)&x,    g_x);
    cudaGetSymbolAddress((void**)&h,    g_h);
    cudaGetSymbolAddress((void**)&qkv,  g_qkv);
    cudaGetSymbolAddress((void**)&ob,   g_o);
    cudaGetSymbolAddress((void**)&midb, g_midb);
    cudaGetSymbolAddress((void**)&tmp,  g_tmp);
    cudaGetSymbolAddress((void**)&wt,   g_wt);
    cudaGetSymbolAddress((void**)&cat,  g_cat);

    cudaFuncSetAttribute((const void*)hmma_gemm_kernel<1>,             cudaFuncAttributeMaxDynamicSharedMemorySize, GSMEM);
    cudaFuncSetAttribute((const void*)hmma_gemm_kernel<3>,             cudaFuncAttributeMaxDynamicSharedMemorySize, GSMEM);
    cudaFuncSetAttribute((const void*)hmma_ln_kernel<__nv_bfloat16>,   cudaFuncAttributeMaxDynamicSharedMemorySize, GSMEM2);
    cudaFuncSetAttribute((const void*)hmma_ln_kernel<float>,           cudaFuncAttributeMaxDynamicSharedMemorySize, GSMEM2);

    detect_cat_kernel<<<1, 256>>>(smk, hmk, gmk, cat);

    const size_t OFF_QKV = 0, OFF_WO = 196608, OFF_W1 = 262144, OFF_W2 = 524288, LSZ = 786432;
    transpose_bf16_kernel<<<dim3(H3 / 32, Hdim / 32, Lnum), dim3(32, 8)>>>(
        Wqkv, wt + OFF_QKV, Hdim, H3, (size_t)Hdim * H3, LSZ);
    transpose_bf16_kernel<<<dim3(Hdim / 32, Hdim / 32, Lnum), dim3(32, 8)>>>(
        Wo, wt + OFF_WO, Hdim, Hdim, (size_t)Hdim * Hdim, LSZ);
    transpose_bf16_kernel<<<dim3(H4 / 32, Hdim / 32, Lnum), dim3(32, 8)>>>(
        W1, wt + OFF_W1, Hdim, H4, (size_t)Hdim * H4, LSZ);
    transpose_bf16_kernel<<<dim3(Hdim / 32, H4 / 32, Lnum), dim3(32, 8)>>>(
        W2, wt + OFF_W2, H4, Hdim, (size_t)H4 * Hdim, LSZ);

    embed_kernel<<<NTOK, 256>>>(act, m_idx, cat, Ws, bs, Wh, bh, Wg, Wact, pos, x);
    ln_warp_kernel<<<NTOK / 8, 256>>>(x, h, ln1_s, ln1_b);

    for (int l = 0; l < Lnum; l++) {
        lora_tmp_kernel<<<NTOK / 8, 256>>>(h, loraA + (size_t)l * Mnum * Hdim * RANKv, m_idx, tmp);
        // qkv = h @ WqkvT + bqkv + lora   (128x128 kernel)
        hmma_gemm_kernel<3><<<dim3(H3 / 128, NTOK / 128), 256, GSMEM>>>(
            h, wt + l * LSZ + OFF_QKV, qkv, bqkv + l * H3,
            tmp, loraB + (size_t)l * Mnum * RANKv * H3, m_idx, Hdim, H3);
        attn_kernel<<<dim3(NSEQ, HEADS), 128>>>(qkv, ob, m_idx);
        // x += g1*(o @ WoT + bo); h = LN2(x)   (64x256 fused-LN kernel)
        hmma_ln_kernel<__nv_bfloat16><<<dim3(1, NTOK / 64), 256, GSMEM2>>>(
            ob, wt + l * LSZ + OFF_WO, x, bo + l * Hdim, g1 + l * Hdim,
            ln2_s + l * Hdim, ln2_b + l * Hdim, h, Hdim);
        // midb = gelu(h @ W1T + b1)   (128x128 kernel)
        hmma_gemm_kernel<1><<<dim3(H4 / 128, NTOK / 128), 256, GSMEM>>>(
            h, wt + l * LSZ + OFF_W1, midb, b1 + l * H4,
            nullptr, nullptr, nullptr, Hdim, H4);
        // x += g2*(midb @ W2T + b2); h = LN1[l+1](x) or out = LNf(x)
        if (l < Lnum - 1) {
            hmma_ln_kernel<__nv_bfloat16><<<dim3(1, NTOK / 64), 256, GSMEM2>>>(
                midb, wt + l * LSZ + OFF_W2, x, b2 + l * Hdim, g2 + l * Hdim,
                ln1_s + (l + 1) * Hdim, ln1_b + (l + 1) * Hdim, h, H4);
        } else {
            hmma_ln_kernel<float><<<dim3(1, NTOK / 64), 256, GSMEM2>>>(
                midb, wt + l * LSZ + OFF_W2, x, b2 + l * Hdim, g2 + l * Hdim,
                lnf_s, lnf_b, out, H4);
        }
    }
}